// round 12
// baseline (speedup 1.0000x reference)
#include <cuda_runtime.h>

#define B_SZ 256
#define T_SZ 2000
#define F_SZ 128

#define CHUNK   64                 // timesteps per pipeline chunk
#define NCHUNK  32                 // ceil(2000/64); last chunk has 16 valid
#define NBUF    8                  // smem ring depth
#define DOT_WARPS 8
#define T_PER_WARP 8               // rows per dot warp per chunk
#define THREADS (32 * (DOT_WARPS + 1))  // 288: warp 0 = scan, warps 1..8 = dot

// BETA = sigmoid(2.0), VTH = 1.0
#define BETA_F 0.8807970779778823f

// 16 distinct physical barriers (0..15); we never use __syncthreads(), so
// barrier 0 is ours. FULL(i)=i, EMPTY(i)=8+i. 1:1 arrive/sync alternation.
#define BAR_FULL(i)  ((i) & 7)
#define BAR_EMPTY(i) (8 + ((i) & 7))

__device__ __forceinline__ void bar_sync(int id) {
    asm volatile("bar.sync %0, %1;" :: "r"(id), "n"(THREADS) : "memory");
}
__device__ __forceinline__ void bar_arrive(int id) {
    asm volatile("bar.arrive %0, %1;" :: "r"(id), "n"(THREADS) : "memory");
}

// One LIF step, pure register code, exact reference rounding:
// u = fma(beta, v, c); w = u-1 and p = (u>=1) branch off u in parallel;
// v' = p ? w : u; spike = p ? 1 : 0 (off the critical chain).
__device__ __forceinline__ float lif_step(float& v, float c) {
    float u = fmaf(BETA_F, v, c);
    float w = u - 1.0f;
    bool  p = (u >= 1.0f);
    v = p ? w : u;
    return p ? 1.0f : 0.0f;
}

__global__ void __launch_bounds__(THREADS, 2) lif_fused_kernel(
    const float* __restrict__ x, const float* __restrict__ W,
    const float* __restrict__ bias, float* __restrict__ out, int out_size)
{
    __shared__ float cur_s[NBUF][CHUNK];

    const int b    = blockIdx.x;          // batch row
    const int wid  = threadIdx.x >> 5;
    const int lane = threadIdx.x & 31;

    if (wid > 0) {
        // ================= producers: dot warps 1..8 (unchanged R11) ========
        const int sub = lane & 7;
        const int grp = lane >> 3;

        float4 w4[4];
        #pragma unroll
        for (int j = 0; j < 4; ++j)
            w4[j] = reinterpret_cast<const float4*>(W)[sub + 8 * j];
        const float bias_v = bias[0];

        const int slice0 = (wid - 1) * T_PER_WARP;
        const float4* X4 = reinterpret_cast<const float4*>(
            x + (size_t)b * T_SZ * F_SZ);

        auto load_batch = [&](float4 (&dst)[2][4], int c) {
            const int t0 = c * CHUNK + slice0;
            #pragma unroll
            for (int p = 0; p < 2; ++p) {
                int trow = t0 + p * 4 + grp;
                trow = (trow < T_SZ) ? trow : (T_SZ - 1);   // clamp tail
                const float4* rp = X4 + (size_t)trow * (F_SZ / 4) + sub;
                #pragma unroll
                for (int j = 0; j < 4; ++j)
                    dst[p][j] = rp[8 * j];
            }
        };

        auto reduce_store = [&](const float4 (&src)[2][4], int c) {
            const int buf = c & (NBUF - 1);
            const int t0  = c * CHUNK + slice0;
            #pragma unroll
            for (int p = 0; p < 2; ++p) {
                float s = 0.0f;
                #pragma unroll
                for (int j = 0; j < 4; ++j) {
                    s = fmaf(src[p][j].x, w4[j].x, s);
                    s = fmaf(src[p][j].y, w4[j].y, s);
                    s = fmaf(src[p][j].z, w4[j].z, s);
                    s = fmaf(src[p][j].w, w4[j].w, s);
                }
                s += __shfl_xor_sync(0xFFFFFFFFu, s, 4);
                s += __shfl_xor_sync(0xFFFFFFFFu, s, 2);
                s += __shfl_xor_sync(0xFFFFFFFFu, s, 1);
                const int trow = t0 + p * 4 + grp;
                if (sub == 0 && trow < T_SZ)
                    cur_s[buf][trow - c * CHUNK] = s + bias_v;
            }
        };

        float4 xv[2][4];
        float4 xn[2][4];
        load_batch(xv, 0);

        #pragma unroll 1
        for (int c = 0; c < NCHUNK; c += 2) {
            load_batch(xn, c + 1);
            bar_sync(BAR_EMPTY(c));
            reduce_store(xv, c);
            bar_arrive(BAR_FULL(c));

            const int c2 = (c + 2 < NCHUNK) ? c + 2 : NCHUNK - 1;
            load_batch(xv, c2);
            bar_sync(BAR_EMPTY(c + 1));
            reduce_store(xn, c + 1);
            bar_arrive(BAR_FULL(c + 1));
        }
    } else {
        // ================= consumer: scan warp 0 =================
        #pragma unroll
        for (int i = 0; i < NBUF; ++i)
            bar_arrive(BAR_EMPTY(i));   // prime the ring

        float v = 0.0f;
        float* out_row = out + (size_t)b * T_SZ;

        for (int c = 0; c < NCHUNK; ++c) {
            bar_sync(BAR_FULL(c));      // wait for all 8 producer arrivals

            if (lane == 0) {
                const int buf   = c & (NBUF - 1);
                const int tbase = c * CHUNK;
                const int ngrp  = ((c == NCHUNK - 1) ? (T_SZ - tbase) : CHUNK) / 4;
                const float4* cs = reinterpret_cast<const float4*>(&cur_s[buf][0]);
                float4* op = reinterpret_cast<float4*>(out_row + tbase);

                float4 cu = cs[0];                    // prefetch group 0
                #pragma unroll 4
                for (int g = 0; g < ngrp; ++g) {
                    float4 nxt = cu;
                    if (g + 1 < ngrp) nxt = cs[g + 1];  // prefetch next group
                    // pure register math — no address-of on float4
                    float s0 = lif_step(v, cu.x);
                    float s1 = lif_step(v, cu.y);
                    float s2 = lif_step(v, cu.z);
                    float s3 = lif_step(v, cu.w);
                    op[g] = make_float4(s0, s1, s2, s3);
                    cu = nxt;
                }
            }

            bar_arrive(BAR_EMPTY(c));   // release ring slot
        }

        // final membrane potential vT
        if (lane == 0 && out_size > B_SZ * T_SZ)
            out[B_SZ * T_SZ + b] = v;
    }
}

extern "C" void kernel_launch(void* const* d_in, const int* in_sizes, int n_in,
                              void* d_out, int out_size)
{
    const float* x    = (const float*)d_in[0];  // [256, 2000, 128] fp32
    const float* W    = (const float*)d_in[1];  // [128, 1] fp32
    const float* bias = (const float*)d_in[2];  // [1] fp32
    float* out = (float*)d_out;                 // spikes [256*2000] then vT [256]

    lif_fused_kernel<<<B_SZ, THREADS>>>(x, W, bias, out, out_size);
}